// round 2
// baseline (speedup 1.0000x reference)
#include <cuda_runtime.h>
#include <cuda_fp16.h>
#include <cstdint>

#define DEV __device__ __forceinline__

namespace {
constexpr int NPTS = 131072;
constexpr int MT = 128;      // M tile per CTA
constexpr int THREADS = 512; // 16 warps: 4(M) x 4(N)
constexpr int KC = 32;       // K chunk
constexpr int AS = 264;      // activation row stride (halves)
constexpr int WS = 40;       // weight/feature chunk row stride (halves)
constexpr int K0 = 544;      // layer-0 K (515 padded)
constexpr int SQ_OFF = 256 * K0;
constexpr int SMEM_BYTES = 208896;
constexpr float TWO_PI = 6.2831853071795864769f;
}

// fp16 transposed weights: L0 [256][544], then 8 x [256][256] (W1..4,Wc0,Wc1,Wn0,Wn1)
__device__ __half g_Wt[256 * 544 + 8 * 65536];

struct Smem {
  __half *actA, *actB, *wbuf, *fbuf;
  float *sB, *sx, *sbias, *sWc2, *sWn2, *outac;
};
DEV Smem get_smem() {
  extern __shared__ char raw[];
  Smem s; __half* h = (__half*)raw;
  s.actA = h; s.actB = h + 33792; s.wbuf = h + 67584; s.fbuf = h + 88064;
  float* f = (float*)(h + 98304);
  s.sB = f; s.sx = f + 768; s.sbias = f + 1280;
  s.sWc2 = f + 1536; s.sWn2 = f + 2304; s.outac = f + 2560;
  return s;
}

DEV void cp16(void* s, const void* g) {
  uint32_t sa = (uint32_t)__cvta_generic_to_shared(s);
  asm volatile("cp.async.ca.shared.global [%0], [%1], 16;\n" :: "r"(sa), "l"(g));
}
DEV void cp_commit() { asm volatile("cp.async.commit_group;\n"); }
template <int N> DEV void cp_wait() { asm volatile("cp.async.wait_group %0;\n" :: "n"(N)); }

DEV void mma16816(float* d, const uint32_t* a, uint32_t b0, uint32_t b1) {
  asm volatile(
      "mma.sync.aligned.m16n8k16.row.col.f32.f16.f16.f32 "
      "{%0,%1,%2,%3}, {%4,%5,%6,%7}, {%8,%9}, {%0,%1,%2,%3};\n"
      : "+f"(d[0]), "+f"(d[1]), "+f"(d[2]), "+f"(d[3])
      : "r"(a[0]), "r"(a[1]), "r"(a[2]), "r"(a[3]), "r"(b0), "r"(b1));
}
DEV float frelu(float v) { return fmaxf(v, 0.0f); }

// Cody-Waite pi-reduction + degree-9/10 polys; abs err ~4e-6, fast-math safe.
DEV void fsincos(float x, float& s, float& c) {
  float qf = rintf(x * 0.3183098861837907f);
  float r = fmaf(qf, -3.1414794921875f, x);
  r = fmaf(qf, -1.1315941810607910156e-4f, r);
  r = fmaf(qf, -1.9841872589410058936e-9f, r);
  float r2 = r * r;
  float sp = fmaf(r2, 2.7557319e-6f, -1.9841270e-4f);
  sp = fmaf(r2, sp, 8.3333333e-3f);
  sp = fmaf(r2, sp, -1.6666667e-1f);
  s = fmaf(r * r2, sp, r);
  float cp = fmaf(r2, -2.7557319e-7f, 2.4801587e-5f);
  cp = fmaf(r2, cp, -1.3888889e-3f);
  cp = fmaf(r2, cp, 4.1666667e-2f);
  cp = fmaf(r2, cp, -0.5f);
  c = fmaf(r2, cp, 1.0f);
  if (((int)qf) & 1) { s = -s; c = -c; }
}

__global__ void prep_weights(const float* W0, const float* W1, const float* W2,
                             const float* W3, const float* W4, const float* Wc0,
                             const float* Wc1, const float* Wn0, const float* Wn1) {
  int tid = blockIdx.x * blockDim.x + threadIdx.x;
  const int total = SQ_OFF + 8 * 65536;
  if (tid >= total) return;
  float v;
  if (tid < SQ_OFF) {
    int n = tid / K0, k = tid % K0;
    v = (k < 515) ? W0[k * 256 + n] : 0.0f;
  } else {
    int r = tid - SQ_OFF;
    int layer = r >> 16, n = (r >> 8) & 255, k = r & 255;
    const float* Ws[8] = {W1, W2, W3, W4, Wc0, Wc1, Wn0, Wn1};
    v = Ws[layer][k * 256 + n];
  }
  g_Wt[tid] = __float2half(v);
}

DEV void load_wchunk(__half* dst, const __half* gW, int Kfull, int c, int tid) {
#pragma unroll
  for (int i = 0; i < 2; i++) {
    int op = tid + i * THREADS;
    int n = op >> 2, seg = op & 3;
    cp16(dst + n * WS + seg * 8, gW + n * Kfull + c * KC + seg * 8);
  }
}

// Layer-0 feature chunk c into dst[128][32] (stride WS): [x, sin, cos, pad]*alpha
DEV void gen_feat(__half* dst, int c, int tid, float t_over_tau) {
  Smem sm = get_smem();
#pragma unroll
  for (int i = 0; i < 8; i++) {
    int idx = tid + i * THREADS;
    int m = idx >> 5, kk = idx & 31, kg = c * KC + kk;
    float v = 0.0f;
    if (kg < 3) {
      v = sm.sx[m * 4 + kg];
    } else if (kg < 515) {
      int j = (kg < 259) ? (kg - 3) : (kg - 259);
      float p = sm.sx[m * 4 + 0] * sm.sB[j];
      p = fmaf(sm.sx[m * 4 + 1], sm.sB[256 + j], p);
      p = fmaf(sm.sx[m * 4 + 2], sm.sB[512 + j], p);
      float sv, cv; fsincos(p * TWO_PI, sv, cv);
      float a = fminf(fmaxf(t_over_tau - (float)j, 0.0f), 1.0f);
      v = ((kg < 259) ? sv : cv) * a;
    }
    dst[m * WS + kk] = __float2half(v);
  }
}

// MODE 0: fp16 activations -> sOut. MODE 1: dot with Wc2 -> outac. MODE 2: dot Wn2.
template <int MODE, bool L0>
__device__ __noinline__ void run_layer(const __half* gW, int Kfull, const float* gbias,
                                       const __half* sIn, __half* sOut, float t_over_tau) {
  Smem sm = get_smem();
  const int tid = threadIdx.x, lane = tid & 31, wid = tid >> 5;
  const int wm = wid >> 2, wn = wid & 3, grp = lane >> 2, qp = lane & 3;

  if (tid < 256) sm.sbias[tid] = gbias[tid];
  if (MODE != 0 && tid < 512) sm.outac[tid] = 0.0f;

  float acc[2][8][4];
#pragma unroll
  for (int a = 0; a < 2; a++)
#pragma unroll
    for (int b = 0; b < 8; b++)
#pragma unroll
      for (int d = 0; d < 4; d++) acc[a][b][d] = 0.0f;

  const int C = Kfull / KC;
  load_wchunk(sm.wbuf, gW, Kfull, 0, tid);
  cp_commit();
  if (L0) gen_feat(sm.fbuf, 0, tid, t_over_tau);

  for (int c = 0; c < C; c++) {
    const __half* wcur = sm.wbuf + (c & 1) * (256 * WS);
    if (c + 1 < C) {
      load_wchunk(sm.wbuf + ((c + 1) & 1) * (256 * WS), gW, Kfull, c + 1, tid);
      cp_commit();
      if (L0) gen_feat(sm.fbuf + ((c + 1) & 1) * (MT * WS), c + 1, tid, t_over_tau);
      cp_wait<1>();
    } else {
      cp_wait<0>();
    }
    __syncthreads();

    const __half* Ab = L0 ? (sm.fbuf + (c & 1) * (MT * WS)) : sIn;
    const int ast = L0 ? WS : AS;
    const int koff = L0 ? 0 : c * KC;

#pragma unroll
    for (int ks = 0; ks < KC; ks += 16) {
      const int k = koff + ks;
      uint32_t afr[2][4];
#pragma unroll
      for (int mt = 0; mt < 2; mt++) {
        const __half* ap = Ab + (wm * 32 + mt * 16 + grp) * ast + k + qp * 2;
        afr[mt][0] = *(const uint32_t*)ap;
        afr[mt][1] = *(const uint32_t*)(ap + 8 * ast);
        afr[mt][2] = *(const uint32_t*)(ap + 8);
        afr[mt][3] = *(const uint32_t*)(ap + 8 * ast + 8);
      }
#pragma unroll
      for (int nt = 0; nt < 8; nt++) {
        const __half* bp = wcur + (wn * 64 + nt * 8 + grp) * WS + ks + qp * 2;
        uint32_t b0 = *(const uint32_t*)bp;
        uint32_t b1 = *(const uint32_t*)(bp + 8);
        mma16816(acc[0][nt], afr[0], b0, b1);
        mma16816(acc[1][nt], afr[1], b0, b1);
      }
    }
    __syncthreads();
  }

  if (MODE == 0) {
#pragma unroll
    for (int mt = 0; mt < 2; mt++) {
      const int r0 = wm * 32 + mt * 16 + grp;
#pragma unroll
      for (int nt = 0; nt < 8; nt++) {
        const int col = wn * 64 + nt * 8 + qp * 2;
        float bx = sm.sbias[col], by = sm.sbias[col + 1];
        *(__half2*)(sOut + r0 * AS + col) =
            __floats2half2_rn(frelu(acc[mt][nt][0] + bx), frelu(acc[mt][nt][1] + by));
        *(__half2*)(sOut + (r0 + 8) * AS + col) =
            __floats2half2_rn(frelu(acc[mt][nt][2] + bx), frelu(acc[mt][nt][3] + by));
      }
    }
    __syncthreads();
  } else {
    constexpr int NJ = (MODE == 1) ? 3 : 1;
    float part[2][2][NJ];
#pragma unroll
    for (int a = 0; a < 2; a++)
#pragma unroll
      for (int b = 0; b < 2; b++)
#pragma unroll
        for (int j = 0; j < NJ; j++) part[a][b][j] = 0.0f;
#pragma unroll
    for (int mt = 0; mt < 2; mt++)
#pragma unroll
      for (int nt = 0; nt < 8; nt++) {
        const int col = wn * 64 + nt * 8 + qp * 2;
        float bx = sm.sbias[col], by = sm.sbias[col + 1];
        float v0 = frelu(acc[mt][nt][0] + bx), v1 = frelu(acc[mt][nt][1] + by);
        float v2 = frelu(acc[mt][nt][2] + bx), v3 = frelu(acc[mt][nt][3] + by);
#pragma unroll
        for (int j = 0; j < NJ; j++) {
          float w0 = (MODE == 1) ? sm.sWc2[col * 3 + j] : sm.sWn2[col];
          float w1 = (MODE == 1) ? sm.sWc2[(col + 1) * 3 + j] : sm.sWn2[col + 1];
          part[mt][0][j] += v0 * w0 + v1 * w1;
          part[mt][1][j] += v2 * w0 + v3 * w1;
        }
      }
#pragma unroll
    for (int mt = 0; mt < 2; mt++)
#pragma unroll
      for (int rh = 0; rh < 2; rh++)
#pragma unroll
        for (int j = 0; j < NJ; j++) {
          float p = part[mt][rh][j];
          p += __shfl_xor_sync(0xffffffffu, p, 1);
          p += __shfl_xor_sync(0xffffffffu, p, 2);
          if (qp == 0)
            atomicAdd(&sm.outac[(wm * 32 + mt * 16 + rh * 8 + grp) * 4 + j], p);
        }
    __syncthreads();
  }
}

struct FusedParams {
  const float *x, *B;
  const float *b0, *b1, *b2, *b3, *b4, *bc0, *bc1, *bc2, *bn0, *bn1, *bn2;
  const float *Wc2, *Wn2;
  const int* t;
  float* out;
};

__global__ void __launch_bounds__(THREADS, 1) fused_mlp(FusedParams p) {
  Smem sm = get_smem();
  const int tid = threadIdx.x;
  const int m0 = blockIdx.x * MT;

  for (int i = tid; i < 384; i += THREADS) {
    int m = i / 3, d = i % 3;
    sm.sx[m * 4 + d] = p.x[(m0 + m) * 3 + d];
  }
  for (int i = tid; i < 768; i += THREADS) sm.sB[i] = p.B[i];
  for (int i = tid; i < 768; i += THREADS) sm.sWc2[i] = p.Wc2[i];
  if (tid < 256) sm.sWn2[tid] = p.Wn2[tid];
  __syncthreads();

  int tb = *p.t;  // int bits or float bits
  float tval = (tb >= 0 && tb < (1 << 20)) ? (float)tb : __int_as_float(tb);
  const float t_over_tau = tval * (6000.0f / 512.0f);  // t / TAU

  const __half* Wq = g_Wt + SQ_OFF;
  run_layer<0, true >(g_Wt,           K0,  p.b0,  nullptr, sm.actB, t_over_tau);
  run_layer<0, false>(Wq + 0 * 65536, 256, p.b1,  sm.actB, sm.actA, 0.0f);
  run_layer<0, false>(Wq + 1 * 65536, 256, p.b2,  sm.actA, sm.actB, 0.0f);
  run_layer<0, false>(Wq + 2 * 65536, 256, p.b3,  sm.actB, sm.actA, 0.0f);
  run_layer<0, false>(Wq + 3 * 65536, 256, p.b4,  sm.actA, sm.actB, 0.0f);  // h in actB
  run_layer<0, false>(Wq + 4 * 65536, 256, p.bc0, sm.actB, sm.actA, 0.0f);
  run_layer<1, false>(Wq + 5 * 65536, 256, p.bc1, sm.actA, nullptr, 0.0f);

  if (tid < 384) {
    int m = tid / 3, j = tid % 3;
    p.out[(m0 + m) * 3 + j] = tanhf(sm.outac[m * 4 + j] + p.bc2[j]) * 0.5f;
  }
  run_layer<0, false>(Wq + 6 * 65536, 256, p.bn0, sm.actB, sm.actA, 0.0f);
  run_layer<2, false>(Wq + 7 * 65536, 256, p.bn1, sm.actA, nullptr, 0.0f);

  if (tid < 128)
    p.out[3 * NPTS + m0 + tid] = tanhf(sm.outac[tid * 4] + p.bn2[0]) * 0.1f;
}

extern "C" void kernel_launch(void* const* d_in, const int* in_sizes, int n_in,
                              void* d_out, int out_size) {
  int i = 0;
  const float* x = (const float*)d_in[i++];
  const float* B = (const float*)d_in[i++];
  const void* tp = nullptr;
  if (in_sizes[2] == 1) tp = d_in[i++];  // dict order: t at index 2
  const float *W[11], *bias[11];
  for (int j = 0; j < 11; j++) {
    W[j] = (const float*)d_in[i++];
    bias[j] = (const float*)d_in[i++];
  }
  if (!tp && i < n_in) tp = d_in[i++];  // signature order: t last

  cudaFuncSetAttribute(fused_mlp, cudaFuncAttributeMaxDynamicSharedMemorySize, SMEM_BYTES);

  const int total = SQ_OFF + 8 * 65536;
  prep_weights<<<(total + 255) / 256, 256>>>(W[0], W[1], W[2], W[3], W[4],
                                             W[5], W[6], W[8], W[9]);

  FusedParams p;
  p.x = x; p.B = B;
  p.b0 = bias[0]; p.b1 = bias[1]; p.b2 = bias[2]; p.b3 = bias[3]; p.b4 = bias[4];
  p.bc0 = bias[5]; p.bc1 = bias[6]; p.bc2 = bias[7];
  p.bn0 = bias[8]; p.bn1 = bias[9]; p.bn2 = bias[10];
  p.Wc2 = W[7]; p.Wn2 = W[10];
  p.t = (const int*)tp;
  p.out = (float*)d_out;

  fused_mlp<<<NPTS / MT, THREADS, SMEM_BYTES>>>(p);
}